// round 16
// baseline (speedup 1.0000x reference)
#include <cuda_runtime.h>
#include <cuda_fp16.h>
#include <cstdint>

// Problem constants
constexpr int N_ROWS = 32768;          // 8*4096
constexpr int D      = 512;
constexpr int KSZ    = 4096;

// Output layout (float32), reference tuple order
constexpr size_t OFF_F    = 0;
constexpr size_t OFF_LOSS = (size_t)N_ROWS * D;
constexpr size_t OFF_K    = OFF_LOSS + 1;          // NOTE: odd offset -> 4B aligned only
constexpr size_t OFF_ECS  = OFF_K + (size_t)KSZ * D;
constexpr size_t OFF_EMAW = OFF_ECS + KSZ;

// ---------------- device scratch ----------------
__device__ __align__(16) __half g_fh[(size_t)N_ROWS * D];
__device__ __align__(16) __half g_kh[(size_t)KSZ * D];
__device__ __align__(16) __half g_scores[(size_t)N_ROWS * KSZ];   // 256MB approx scores
__device__ __align__(16) float  g_tmin[(size_t)N_ROWS * 128];     // per-row 32-col band mins
__device__ float               g_y2[KSZ];
__device__ int                 g_idx[N_ROWS];
__device__ int                 g_cnt[KSZ];
__device__ int                 g_off[KSZ];
__device__ int                 g_cur[KSZ];
__device__ int                 g_rows[N_ROWS];
__device__ double              g_loss;
__device__ double              g_n;

// ---------------- helpers ----------------
__device__ __forceinline__ uint32_t smem_u32(const void* p) {
    uint32_t a;
    asm("{ .reg .u64 t; cvta.to.shared.u64 t, %1; cvt.u32.u64 %0, t; }" : "=r"(a) : "l"(p));
    return a;
}
__device__ __forceinline__ void cp16(uint32_t s, const void* g) {
    asm volatile("cp.async.cg.shared.global [%0], [%1], 16;" :: "r"(s), "l"(g));
}
__device__ __forceinline__ unsigned int fkey(float v) {
    unsigned int b = __float_as_uint(v);
    return (b & 0x80000000u) ? ~b : (b | 0x80000000u);
}
// m16n8k16 fp16 MMA, fp32 accumulate (baseline PTX, tensor pipe)
__device__ __forceinline__ void mma16(float* d, const uint32_t* a, const uint32_t* b) {
    asm volatile("mma.sync.aligned.m16n8k16.row.col.f32.f16.f16.f32 "
                 "{%0,%1,%2,%3}, {%4,%5,%6,%7}, {%8,%9}, {%0,%1,%2,%3};"
                 : "+f"(d[0]), "+f"(d[1]), "+f"(d[2]), "+f"(d[3])
                 : "r"(a[0]), "r"(a[1]), "r"(a[2]), "r"(a[3]), "r"(b[0]), "r"(b[1]));
}
// mbarrier primitives (baseline PTX, sm_90-level, valid at compute_103)
#define MBAR_INIT(addr, cnt) \
    asm volatile("mbarrier.init.shared.b64 [%0], %1;" :: "r"(addr), "r"(cnt) : "memory")
#define MBAR_ARRIVE(addr) \
    asm volatile("mbarrier.arrive.release.cta.shared::cta.b64 _, [%0];" :: "r"(addr) : "memory")
#define CP_ARRIVE_NOINC(addr) \
    asm volatile("cp.async.mbarrier.arrive.noinc.shared::cta.b64 [%0];" :: "r"(addr) : "memory")
__device__ __forceinline__ void mbar_wait(uint32_t addr, uint32_t parity) {
    asm volatile("{\n\t.reg .pred P;\n\tWL_%=:\n\t"
                 "mbarrier.try_wait.parity.acquire.cta.shared::cta.b64 P, [%0], %1, 0x989680;\n\t"
                 "@P bra.uni WD_%=;\n\tbra.uni WL_%=;\n\tWD_%=:\n\t}"
                 :: "r"(addr), "r"(parity) : "memory");
}

// ---------------- kernel 1: fp16 downcast + scratch zero (fused) ----------------
__global__ void split_kernel(const float* __restrict__ f, const float* __restrict__ Kc) {
    size_t i = (size_t)blockIdx.x * 256 + threadIdx.x;   // covers N_ROWS*D
    g_fh[i] = __float2half_rn(f[i]);
    if (i < (size_t)KSZ * D) g_kh[i] = __float2half_rn(Kc[i]);
    if (i < KSZ) g_cnt[i] = 0;
    if (i == 0) { g_loss = 0.0; g_n = 0.0; }
}

// ---------------- kernel 2: code norms (fp32 exact) ----------------
__global__ void y2_kernel(const float* __restrict__ Kc) {
    int k = blockIdx.x;
    const float4* kv = (const float4*)(Kc + (size_t)k * D);
    float4 v = kv[threadIdx.x];
    float s = v.x * v.x + v.y * v.y + v.z * v.z + v.w * v.w;
    #pragma unroll
    for (int o = 16; o > 0; o >>= 1) s += __shfl_down_sync(0xffffffffu, s, o);
    __shared__ float sh[4];
    if ((threadIdx.x & 31) == 0) sh[threadIdx.x >> 5] = s;
    __syncthreads();
    if (threadIdx.x == 0) g_y2[k] = sh[0] + sh[1] + sh[2] + sh[3];
}

// ---------------- kernel 3: 1-term fp16 GEMM -> approx scores + band mins ----------------
// CTA tile 256 rows x 128 codes; 16 warps (4m x 4n) of 64x32; KBLK=64; 3 stages.
// Warp-autonomous mbarrier pipeline (no CTA-wide mainloop barriers).
constexpr int KBLK   = 64;             // halves per k-block
constexpr int NKB    = D / KBLK;       // 8
constexpr int STAGES = 3;
constexpr int CODT   = KSZ / 128;      // 32 code tiles (inner for L2 reuse)

// smem stage layout in halves (row stride 72 halves = 36 words: banks 4g+c,
// conflict-free for both cp.async stores and fragment LDS)
constexpr int AH_H = 0;                // A: 256 x 72
constexpr int BH_H = 18432;            // B: 128 x 72
constexpr int STG_H = 27648;           // halves per stage
constexpr uint32_t STG_B = STG_H * 2;  // 55296 B
constexpr uint32_t SMEM_DYN = STAGES * STG_B;  // 165888 B

__global__ void __launch_bounds__(512, 1)
gemm_kernel() {
    extern __shared__ __half smem[];
    __shared__ float sy2[128];
    __shared__ __align__(8) unsigned long long mb_full[STAGES];
    __shared__ __align__(8) unsigned long long mb_empty[STAGES];

    const uint32_t sbase = smem_u32(smem);
    const uint32_t fullb = smem_u32(mb_full);
    const uint32_t emptyb = smem_u32(mb_empty);
    const int tid = threadIdx.x;
    const int wid = tid >> 5;
    const int lane = tid & 31;
    const int g = lane >> 2;        // groupID
    const int c = lane & 3;         // threadInGroup
    const int wm = wid >> 2;        // 0..3 -> warp rows wm*64
    const int wn = wid & 3;         // 0..3 -> warp cols wn*32
    const int wr = wm * 64;
    const int wc = wn * 32;

    const int codetile = blockIdx.x & (CODT - 1);
    const int rowtile  = blockIdx.x >> 5;
    const int row0  = rowtile * 256;
    const int code0 = codetile * 128;

    if (tid < 128) sy2[tid] = g_y2[code0 + tid];
    if (tid < STAGES) {
        MBAR_INIT(fullb + 8 * tid, 512u);   // one cp-arrive per thread
        MBAR_INIT(emptyb + 8 * tid, 16u);   // one arrive per warp
    }
    __syncthreads();   // barriers + sy2 visible; only CTA-wide sync in kernel

    const __half* fa = g_fh + (size_t)row0 * D;
    const __half* kb_ = g_kh + (size_t)code0 * D;

    // per-thread fill slice: 6 cp.async(16B) + async arrive on full[s]
    auto fill = [&](int kb) {
        const int s = kb % STAGES;
        const uint32_t sb = sbase + (uint32_t)s * STG_B;
        const int koff = kb * KBLK;
        #pragma unroll
        for (int rep = 0; rep < 4; rep++) {           // A: 2048 chunks
            const int idx = tid + rep * 512;
            const int r = idx >> 3, kc = idx & 7;
            cp16(sb + (uint32_t)(r * 144 + kc * 16),
                 fa + (size_t)r * D + koff + kc * 8);
        }
        #pragma unroll
        for (int rep = 0; rep < 2; rep++) {           // B: 1024 chunks
            const int idx = tid + rep * 512;
            const int r = idx >> 3, kc = idx & 7;
            cp16(sb + BH_H * 2 + (uint32_t)(r * 144 + kc * 16),
                 kb_ + (size_t)r * D + koff + kc * 8);
        }
        CP_ARRIVE_NOINC(fullb + 8 * s);
    };

    fill(0);
    fill(1);

    float acc[4][4][4];
    #pragma unroll
    for (int mt = 0; mt < 4; mt++)
        #pragma unroll
        for (int nt = 0; nt < 4; nt++)
            #pragma unroll
            for (int k = 0; k < 4; k++) acc[mt][nt][k] = 0.0f;

    for (int kb = 0; kb < NKB; kb++) {
        const int s = kb % STAGES;
        // prefetch stage for kb+2 (gated on its previous occupant being consumed)
        if (kb + 2 < NKB) {
            const int j = kb + 2, sj = j % STAGES;
            if (j >= STAGES)
                mbar_wait(emptyb + 8 * sj, (uint32_t)((j / STAGES - 1) & 1));
            fill(j);
        }
        // wait for this stage's data
        mbar_wait(fullb + 8 * s, (uint32_t)((kb / STAGES) & 1));

        const __half* S = smem + (size_t)s * STG_H;
        const __half* Sah = S + AH_H;
        const __half* Sbh = S + BH_H;

        #pragma unroll
        for (int ks = 0; ks < 4; ks++) {
            const int k0 = ks * 16;
            uint32_t bh[4][2];
            #pragma unroll
            for (int nt = 0; nt < 4; nt++) {
                const int n = wc + nt * 8 + g;
                bh[nt][0] = *(const uint32_t*)&Sbh[n * 72 + k0 + 2 * c];
                bh[nt][1] = *(const uint32_t*)&Sbh[n * 72 + k0 + 2 * c + 8];
            }
            uint32_t ah[4][4];
            #pragma unroll
            for (int mt = 0; mt < 4; mt++) {
                const int r = wr + mt * 16 + g;
                ah[mt][0] = *(const uint32_t*)&Sah[r * 72 + k0 + 2 * c];
                ah[mt][1] = *(const uint32_t*)&Sah[(r + 8) * 72 + k0 + 2 * c];
                ah[mt][2] = *(const uint32_t*)&Sah[r * 72 + k0 + 2 * c + 8];
                ah[mt][3] = *(const uint32_t*)&Sah[(r + 8) * 72 + k0 + 2 * c + 8];
            }
            #pragma unroll
            for (int mt = 0; mt < 4; mt++)
                #pragma unroll
                for (int nt = 0; nt < 4; nt++)
                    mma16(acc[mt][nt], ah[mt], bh[nt]);
        }
        // this warp is done reading stage s (MMAs issued in-order after LDS)
        if (lane == 0) MBAR_ARRIVE(emptyb + 8 * s);
    }

    // epilogue: write approx scores (fp16) + per-row band mins (fp32)
    #pragma unroll
    for (int mt = 0; mt < 4; mt++) {
        #pragma unroll
        for (int half = 0; half < 2; half++) {
            const int r = row0 + wr + mt * 16 + g + half * 8;
            __half* dst = g_scores + (size_t)r * KSZ + code0;
            float rmin = 3.4e38f;
            #pragma unroll
            for (int nt = 0; nt < 4; nt++) {
                const int col = wc + nt * 8 + c * 2;
                float s0 = sy2[col]     - 2.0f * acc[mt][nt][half * 2 + 0];
                float s1 = sy2[col + 1] - 2.0f * acc[mt][nt][half * 2 + 1];
                *(__half2*)(dst + col) = __floats2half2_rn(s0, s1);
                rmin = fminf(rmin, fminf(s0, s1));
            }
            rmin = fminf(rmin, __shfl_xor_sync(0xffffffffu, rmin, 1));
            rmin = fminf(rmin, __shfl_xor_sync(0xffffffffu, rmin, 2));
            if (c == 0)
                g_tmin[(size_t)r * 128 + codetile * 4 + wn] = rmin;
        }
    }
}

// ---------------- kernel 4: exact argmin via band filter + candidate rescore ----------------
constexpr float MARGIN = 6.0f;   // >> hard error bound (~1.5) of pass-1 scores

__global__ void __launch_bounds__(256, 4)
argmin_kernel(const float* __restrict__ f, const float* __restrict__ Kc) {
    const int w = threadIdx.x >> 5, lane = threadIdx.x & 31;
    const int row = blockIdx.x * 8 + w;

    // pass A: min over 128 band mins
    float4 bm = ((const float4*)(g_tmin + (size_t)row * 128))[lane];
    float m = fminf(fminf(bm.x, bm.y), fminf(bm.z, bm.w));
    #pragma unroll
    for (int o = 16; o > 0; o >>= 1)
        m = fminf(m, __shfl_xor_sync(0xffffffffu, m, o));
    const float thr = m + MARGIN;

    int bmask = (bm.x <= thr ? 1 : 0) | (bm.y <= thr ? 2 : 0)
              | (bm.z <= thr ? 4 : 0) | (bm.w <= thr ? 8 : 0);

    // pass B: enumerate candidates in hot bands, exact fp32 rescore
    const float4* f4 = (const float4*)(f + (size_t)row * D);
    unsigned long long bestk = ~0ULL;
    unsigned bal = __ballot_sync(0xffffffffu, bmask != 0);
    while (bal) {
        const int s = __ffs(bal) - 1; bal &= bal - 1;
        int mb = __shfl_sync(0xffffffffu, bmask, s);
        while (mb) {
            const int q = __ffs(mb) - 1; mb &= mb - 1;
            const int band = s * 4 + q;
            const float sc_h = __half2float(
                g_scores[(size_t)row * KSZ + band * 32 + lane]);
            unsigned cb = __ballot_sync(0xffffffffu, sc_h <= thr);
            while (cb) {
                const int cs = __ffs(cb) - 1; cb &= cb - 1;
                const int cand = band * 32 + cs;
                // warp-cooperative exact fp32 dot
                const float4* k4 = (const float4*)(Kc + (size_t)cand * D);
                float ds = 0.0f;
                #pragma unroll
                for (int qq = 0; qq < 4; qq++) {
                    float4 a = f4[qq * 32 + lane];
                    float4 kk = k4[qq * 32 + lane];
                    ds += a.x * kk.x + a.y * kk.y + a.z * kk.z + a.w * kk.w;
                }
                #pragma unroll
                for (int o = 16; o > 0; o >>= 1)
                    ds += __shfl_xor_sync(0xffffffffu, ds, o);
                const float sc = g_y2[cand] - 2.0f * ds;
                const unsigned long long key =
                    ((unsigned long long)fkey(sc) << 32) | (unsigned)cand;
                bestk = (key < bestk) ? key : bestk;
            }
        }
    }
    if (lane == 0) {
        const int best = (int)(bestk & 0xFFFFFFFFULL);
        g_idx[row] = best;
        atomicAdd(&g_cnt[best], 1);
    }
}

// ---------------- kernel 5: exclusive prefix of counts (single block) ----------------
__global__ void __launch_bounds__(1024, 1) prefix_kernel() {
    __shared__ int warp_tot[32];
    const int tid = threadIdx.x;
    const int lane = tid & 31, wid = tid >> 5;
    const int base = tid * 4;
    const int c0 = g_cnt[base], c1 = g_cnt[base + 1];
    const int c2 = g_cnt[base + 2], c3 = g_cnt[base + 3];
    const int t = c0 + c1 + c2 + c3;
    int v = t;
    #pragma unroll
    for (int o = 1; o < 32; o <<= 1) {
        int u = __shfl_up_sync(0xffffffffu, v, o);
        if (lane >= o) v += u;
    }
    if (lane == 31) warp_tot[wid] = v;
    __syncthreads();
    if (wid == 0) {
        int wv = warp_tot[lane];
        #pragma unroll
        for (int o = 1; o < 32; o <<= 1) {
            int u = __shfl_up_sync(0xffffffffu, wv, o);
            if (lane >= o) wv += u;
        }
        warp_tot[lane] = wv;
    }
    __syncthreads();
    const int excl = v - t + (wid > 0 ? warp_tot[wid - 1] : 0);
    g_off[base]     = excl;             g_cur[base]     = excl;
    g_off[base + 1] = excl + c0;        g_cur[base + 1] = excl + c0;
    g_off[base + 2] = excl + c0 + c1;   g_cur[base + 2] = excl + c0 + c1;
    g_off[base + 3] = excl + c0 + c1 + c2;
    g_cur[base + 3] = excl + c0 + c1 + c2;
}

// ---------------- kernel 6: fill CSR row lists ----------------
__global__ void fill_kernel() {
    const int row = blockIdx.x * 256 + threadIdx.x;
    const int pos = atomicAdd(&g_cur[g_idx[row]], 1);
    g_rows[pos] = row;
}

// ---------------- kernel 7: gather + loss (no atomics on dw) ----------------
__global__ void gather_kernel(const float* __restrict__ f, const float* __restrict__ Kc,
                              float* __restrict__ out) {
    const int row = blockIdx.x * 2 + (threadIdx.x >> 7);
    const int c4  = threadIdx.x & 127;
    const int idx = g_idx[row];
    float4 kv = __ldg((const float4*)(Kc + (size_t)idx * D) + c4);
    float4 fv = __ldg((const float4*)(f + (size_t)row * D) + c4);
    ((float4*)(out + OFF_F))[(size_t)row * (D / 4) + c4] = kv;
    float dx = kv.x - fv.x, dy = kv.y - fv.y, dz = kv.z - fv.z, dw_ = kv.w - fv.w;
    float s = dx * dx + dy * dy + dz * dz + dw_ * dw_;
    #pragma unroll
    for (int o = 16; o > 0; o >>= 1) s += __shfl_down_sync(0xffffffffu, s, o);
    __shared__ float sh[8];
    if ((threadIdx.x & 31) == 0) sh[threadIdx.x >> 5] = s;
    __syncthreads();
    if (threadIdx.x == 0) {
        float tot = 0.0f;
        #pragma unroll
        for (int w = 0; w < 8; w++) tot += sh[w];
        atomicAdd(&g_loss, (double)tot);
    }
}

// ---------------- kernel 8: new_ecs + n ----------------
__global__ void ecs_kernel(const float* __restrict__ ecs, float* __restrict__ out) {
    const int i = blockIdx.x * 256 + threadIdx.x;
    float newc = ecs[i] * 0.99f + 0.01f * (float)g_cnt[i];
    out[OFF_ECS + i] = newc;
    float s = newc;
    #pragma unroll
    for (int o = 16; o > 0; o >>= 1) s += __shfl_down_sync(0xffffffffu, s, o);
    __shared__ float sh[8];
    if ((threadIdx.x & 31) == 0) sh[threadIdx.x >> 5] = s;
    __syncthreads();
    if (threadIdx.x == 0) {
        float tot = 0.0f;
        #pragma unroll
        for (int w = 0; w < 8; w++) tot += sh[w];
        atomicAdd(&g_n, (double)tot);
    }
}

// ---------------- kernel 9: dw (CSR gather-sum) + new_ema_w + new_K + loss ----------------
// NOTE: out+OFF_K / out+OFF_EMAW are 4B-aligned only (odd float offset) ->
// scalar stores; loads from f/emaw stay vectorized.
__global__ void __launch_bounds__(128, 8)
final_kernel(const float* __restrict__ f, const float* __restrict__ emaw,
             float* __restrict__ out) {
    const int k = blockIdx.x;          // code
    const int tid = threadIdx.x;       // 128 threads -> one float4 each (D=512)
    const int start = g_off[k];
    const int cnt   = g_cnt[k];
    float4 dw = make_float4(0.0f, 0.0f, 0.0f, 0.0f);
    for (int j = 0; j < cnt; j++) {
        const int r = g_rows[start + j];
        float4 a = __ldg((const float4*)(f + (size_t)r * D) + tid);
        dw.x += a.x; dw.y += a.y; dw.z += a.z; dw.w += a.w;
    }
    float4 w = __ldg((const float4*)(emaw + (size_t)k * D) + tid);
    float4 neww = make_float4(w.x * 0.99f + 0.01f * dw.x,
                              w.y * 0.99f + 0.01f * dw.y,
                              w.z * 0.99f + 0.01f * dw.z,
                              w.w * 0.99f + 0.01f * dw.w);
    const size_t eb = OFF_EMAW + (size_t)k * D + tid * 4;
    out[eb + 0] = neww.x;
    out[eb + 1] = neww.y;
    out[eb + 2] = neww.z;
    out[eb + 3] = neww.w;
    const float nn = (float)g_n;
    const float newc = out[OFF_ECS + k];
    const float smoothed = (newc + 1e-5f) / (nn + 4096.0f * 1e-5f) * nn;
    const float invs = 1.0f / smoothed;
    const size_t kb2 = OFF_K + (size_t)k * D + tid * 4;
    out[kb2 + 0] = neww.x * invs;
    out[kb2 + 1] = neww.y * invs;
    out[kb2 + 2] = neww.z * invs;
    out[kb2 + 3] = neww.w * invs;
    if (k == 0 && tid == 0)
        out[OFF_LOSS] = (float)(g_loss / ((double)N_ROWS * (double)D));
}

extern "C" void kernel_launch(void* const* d_in, const int* in_sizes, int n_in,
                              void* d_out, int out_size) {
    const float* f    = (const float*)d_in[0];  // [8,4096,512]
    const float* Kc   = (const float*)d_in[1];  // [4096,512]
    const float* ecs  = (const float*)d_in[2];  // [4096]
    const float* emaw = (const float*)d_in[3];  // [4096,512]
    float* out = (float*)d_out;

    cudaFuncSetAttribute(gemm_kernel, cudaFuncAttributeMaxDynamicSharedMemorySize, SMEM_DYN);

    split_kernel<<<(N_ROWS * D) / 256, 256>>>(f, Kc);
    y2_kernel<<<KSZ, 128>>>(Kc);
    gemm_kernel<<<(N_ROWS / 256) * CODT, 512, SMEM_DYN>>>();
    argmin_kernel<<<N_ROWS / 8, 256>>>(f, Kc);
    prefix_kernel<<<1, 1024>>>();
    fill_kernel<<<N_ROWS / 256, 256>>>();
    gather_kernel<<<N_ROWS / 2, 256>>>(f, Kc, out);
    ecs_kernel<<<KSZ / 256, 256>>>(ecs, out);
    final_kernel<<<KSZ, 128>>>(f, emaw, out);
}

// round 17
// speedup vs baseline: 1.0353x; 1.0353x over previous
#include <cuda_runtime.h>
#include <cuda_fp16.h>
#include <cstdint>

// Problem constants
constexpr int N_ROWS = 32768;          // 8*4096
constexpr int D      = 512;
constexpr int KSZ    = 4096;

// Output layout (float32), reference tuple order
constexpr size_t OFF_F    = 0;
constexpr size_t OFF_LOSS = (size_t)N_ROWS * D;
constexpr size_t OFF_K    = OFF_LOSS + 1;          // odd offset -> 4B aligned only
constexpr size_t OFF_ECS  = OFF_K + (size_t)KSZ * D;
constexpr size_t OFF_EMAW = OFF_ECS + KSZ;

// ---------------- device scratch ----------------
__device__ __align__(16) __half g_fh[(size_t)N_ROWS * D];
__device__ __align__(16) __half g_kh[(size_t)KSZ * D];
__device__ __align__(16) __half g_scores[(size_t)N_ROWS * KSZ];   // 256MB approx scores
__device__ __align__(16) float  g_tmin[(size_t)N_ROWS * 128];     // per-row 32-col band mins
__device__ float               g_y2[KSZ];
__device__ float               g_counts[KSZ];
__device__ float               g_dw[(size_t)KSZ * D];
__device__ double              g_loss;
__device__ double              g_n;

// ---------------- helpers ----------------
__device__ __forceinline__ uint32_t smem_u32(const void* p) {
    uint32_t a;
    asm("{ .reg .u64 t; cvta.to.shared.u64 t, %1; cvt.u32.u64 %0, t; }" : "=r"(a) : "l"(p));
    return a;
}
__device__ __forceinline__ void cp16(uint32_t s, const void* g) {
    asm volatile("cp.async.cg.shared.global [%0], [%1], 16;" :: "r"(s), "l"(g));
}
__device__ __forceinline__ unsigned int fkey(float v) {
    unsigned int b = __float_as_uint(v);
    return (b & 0x80000000u) ? ~b : (b | 0x80000000u);
}
// m16n8k16 fp16 MMA, fp32 accumulate (baseline PTX, tensor pipe)
__device__ __forceinline__ void mma16(float* d, const uint32_t* a, const uint32_t* b) {
    asm volatile("mma.sync.aligned.m16n8k16.row.col.f32.f16.f16.f32 "
                 "{%0,%1,%2,%3}, {%4,%5,%6,%7}, {%8,%9}, {%0,%1,%2,%3};"
                 : "+f"(d[0]), "+f"(d[1]), "+f"(d[2]), "+f"(d[3])
                 : "r"(a[0]), "r"(a[1]), "r"(a[2]), "r"(a[3]), "r"(b[0]), "r"(b[1]));
}
// mbarrier primitives (baseline PTX, sm_90-level, valid at compute_103)
#define MBAR_INIT(addr, cnt) \
    asm volatile("mbarrier.init.shared.b64 [%0], %1;" :: "r"(addr), "r"(cnt) : "memory")
#define MBAR_ARRIVE(addr) \
    asm volatile("mbarrier.arrive.release.cta.shared::cta.b64 _, [%0];" :: "r"(addr) : "memory")
#define CP_ARRIVE_NOINC(addr) \
    asm volatile("cp.async.mbarrier.arrive.noinc.shared::cta.b64 [%0];" :: "r"(addr) : "memory")
__device__ __forceinline__ void mbar_wait(uint32_t addr, uint32_t parity) {
    asm volatile("{\n\t.reg .pred P;\n\tWL_%=:\n\t"
                 "mbarrier.try_wait.parity.acquire.cta.shared::cta.b64 P, [%0], %1, 0x989680;\n\t"
                 "@P bra.uni WD_%=;\n\tbra.uni WL_%=;\n\tWD_%=:\n\t}"
                 :: "r"(addr), "r"(parity) : "memory");
}

// ---------------- kernel 1: fp16 downcast + scratch zero (fused) ----------------
__global__ void split_kernel(const float* __restrict__ f, const float* __restrict__ Kc) {
    size_t i = (size_t)blockIdx.x * 256 + threadIdx.x;   // covers N_ROWS*D
    g_fh[i] = __float2half_rn(f[i]);
    if (i < (size_t)KSZ * D) {
        g_kh[i] = __float2half_rn(Kc[i]);
        g_dw[i] = 0.0f;
    }
    if (i < KSZ) g_counts[i] = 0.0f;
    if (i == 0) { g_loss = 0.0; g_n = 0.0; }
}

// ---------------- kernel 2: code norms (fp32 exact) ----------------
__global__ void y2_kernel(const float* __restrict__ Kc) {
    int k = blockIdx.x;
    const float4* kv = (const float4*)(Kc + (size_t)k * D);
    float4 v = kv[threadIdx.x];
    float s = v.x * v.x + v.y * v.y + v.z * v.z + v.w * v.w;
    #pragma unroll
    for (int o = 16; o > 0; o >>= 1) s += __shfl_down_sync(0xffffffffu, s, o);
    __shared__ float sh[4];
    if ((threadIdx.x & 31) == 0) sh[threadIdx.x >> 5] = s;
    __syncthreads();
    if (threadIdx.x == 0) g_y2[k] = sh[0] + sh[1] + sh[2] + sh[3];
}

// ---------------- kernel 3: 1-term fp16 GEMM -> approx scores + band mins ----------------
// CTA tile 256 rows x 128 codes; 16 warps (4m x 4n) of 64x32; KBLK=64; 3 stages.
// Warp-autonomous mbarrier pipeline (no CTA-wide mainloop barriers).
constexpr int KBLK   = 64;             // halves per k-block
constexpr int NKB    = D / KBLK;       // 8
constexpr int STAGES = 3;
constexpr int CODT   = KSZ / 128;      // 32 code tiles (inner for L2 reuse)

// smem stage layout in halves (row stride 72 halves = 36 words: banks 4g+c,
// conflict-free for both cp.async stores and fragment LDS)
constexpr int AH_H = 0;                // A: 256 x 72
constexpr int BH_H = 18432;            // B: 128 x 72
constexpr int STG_H = 27648;           // halves per stage
constexpr uint32_t STG_B = STG_H * 2;  // 55296 B
constexpr uint32_t SMEM_DYN = STAGES * STG_B;  // 165888 B

__global__ void __launch_bounds__(512, 1)
gemm_kernel() {
    extern __shared__ __half smem[];
    __shared__ float sy2[128];
    __shared__ __align__(8) unsigned long long mb_full[STAGES];
    __shared__ __align__(8) unsigned long long mb_empty[STAGES];

    const uint32_t sbase = smem_u32(smem);
    const uint32_t fullb = smem_u32(mb_full);
    const uint32_t emptyb = smem_u32(mb_empty);
    const int tid = threadIdx.x;
    const int wid = tid >> 5;
    const int lane = tid & 31;
    const int g = lane >> 2;        // groupID
    const int c = lane & 3;         // threadInGroup
    const int wm = wid >> 2;        // 0..3 -> warp rows wm*64
    const int wn = wid & 3;         // 0..3 -> warp cols wn*32
    const int wr = wm * 64;
    const int wc = wn * 32;

    const int codetile = blockIdx.x & (CODT - 1);
    const int rowtile  = blockIdx.x >> 5;
    const int row0  = rowtile * 256;
    const int code0 = codetile * 128;

    if (tid < 128) sy2[tid] = g_y2[code0 + tid];
    if (tid < STAGES) {
        MBAR_INIT(fullb + 8 * tid, 512u);   // one cp-arrive per thread
        MBAR_INIT(emptyb + 8 * tid, 16u);   // one arrive per warp
    }
    __syncthreads();   // barriers + sy2 visible; only CTA-wide sync in kernel

    const __half* fa = g_fh + (size_t)row0 * D;
    const __half* kb_ = g_kh + (size_t)code0 * D;

    // per-thread fill slice: 6 cp.async(16B) + async arrive on full[s]
    auto fill = [&](int kb) {
        const int s = kb % STAGES;
        const uint32_t sb = sbase + (uint32_t)s * STG_B;
        const int koff = kb * KBLK;
        #pragma unroll
        for (int rep = 0; rep < 4; rep++) {           // A: 2048 chunks
            const int idx = tid + rep * 512;
            const int r = idx >> 3, kc = idx & 7;
            cp16(sb + (uint32_t)(r * 144 + kc * 16),
                 fa + (size_t)r * D + koff + kc * 8);
        }
        #pragma unroll
        for (int rep = 0; rep < 2; rep++) {           // B: 1024 chunks
            const int idx = tid + rep * 512;
            const int r = idx >> 3, kc = idx & 7;
            cp16(sb + BH_H * 2 + (uint32_t)(r * 144 + kc * 16),
                 kb_ + (size_t)r * D + koff + kc * 8);
        }
        CP_ARRIVE_NOINC(fullb + 8 * s);
    };

    fill(0);
    fill(1);

    float acc[4][4][4];
    #pragma unroll
    for (int mt = 0; mt < 4; mt++)
        #pragma unroll
        for (int nt = 0; nt < 4; nt++)
            #pragma unroll
            for (int k = 0; k < 4; k++) acc[mt][nt][k] = 0.0f;

    for (int kb = 0; kb < NKB; kb++) {
        const int s = kb % STAGES;
        // prefetch stage for kb+2 (gated on its previous occupant being consumed)
        if (kb + 2 < NKB) {
            const int j = kb + 2, sj = j % STAGES;
            if (j >= STAGES)
                mbar_wait(emptyb + 8 * sj, (uint32_t)((j / STAGES - 1) & 1));
            fill(j);
        }
        // wait for this stage's data
        mbar_wait(fullb + 8 * s, (uint32_t)((kb / STAGES) & 1));

        const __half* S = smem + (size_t)s * STG_H;
        const __half* Sah = S + AH_H;
        const __half* Sbh = S + BH_H;

        #pragma unroll
        for (int ks = 0; ks < 4; ks++) {
            const int k0 = ks * 16;
            uint32_t bh[4][2];
            #pragma unroll
            for (int nt = 0; nt < 4; nt++) {
                const int n = wc + nt * 8 + g;
                bh[nt][0] = *(const uint32_t*)&Sbh[n * 72 + k0 + 2 * c];
                bh[nt][1] = *(const uint32_t*)&Sbh[n * 72 + k0 + 2 * c + 8];
            }
            uint32_t ah[4][4];
            #pragma unroll
            for (int mt = 0; mt < 4; mt++) {
                const int r = wr + mt * 16 + g;
                ah[mt][0] = *(const uint32_t*)&Sah[r * 72 + k0 + 2 * c];
                ah[mt][1] = *(const uint32_t*)&Sah[(r + 8) * 72 + k0 + 2 * c];
                ah[mt][2] = *(const uint32_t*)&Sah[r * 72 + k0 + 2 * c + 8];
                ah[mt][3] = *(const uint32_t*)&Sah[(r + 8) * 72 + k0 + 2 * c + 8];
            }
            #pragma unroll
            for (int mt = 0; mt < 4; mt++)
                #pragma unroll
                for (int nt = 0; nt < 4; nt++)
                    mma16(acc[mt][nt], ah[mt], bh[nt]);
        }
        // this warp is done reading stage s (MMAs issued in-order after LDS)
        if (lane == 0) MBAR_ARRIVE(emptyb + 8 * s);
    }

    // epilogue: write approx scores (fp16) + per-row band mins (fp32)
    #pragma unroll
    for (int mt = 0; mt < 4; mt++) {
        #pragma unroll
        for (int half = 0; half < 2; half++) {
            const int r = row0 + wr + mt * 16 + g + half * 8;
            __half* dst = g_scores + (size_t)r * KSZ + code0;
            float rmin = 3.4e38f;
            #pragma unroll
            for (int nt = 0; nt < 4; nt++) {
                const int col = wc + nt * 8 + c * 2;
                float s0 = sy2[col]     - 2.0f * acc[mt][nt][half * 2 + 0];
                float s1 = sy2[col + 1] - 2.0f * acc[mt][nt][half * 2 + 1];
                *(__half2*)(dst + col) = __floats2half2_rn(s0, s1);
                rmin = fminf(rmin, fminf(s0, s1));
            }
            rmin = fminf(rmin, __shfl_xor_sync(0xffffffffu, rmin, 1));
            rmin = fminf(rmin, __shfl_xor_sync(0xffffffffu, rmin, 2));
            if (c == 0)
                g_tmin[(size_t)r * 128 + codetile * 4 + wn] = rmin;
        }
    }
}

// ---------------- kernel 4: fused exact argmin + gather + loss + EMA scatter ----------------
// One warp per row: band filter -> exact rescore -> then the same warp writes
// f_ipmlm[row] = K[best], accumulates loss, scatters dw/counts. f row is
// already register-resident from the rescore path.
constexpr float MARGIN = 6.0f;   // >> hard error bound (~1.5) of pass-1 scores

__global__ void __launch_bounds__(256, 4)
argmin_kernel(const float* __restrict__ f, const float* __restrict__ Kc,
              float* __restrict__ out) {
    const int w = threadIdx.x >> 5, lane = threadIdx.x & 31;
    const int row = blockIdx.x * 8 + w;
    __shared__ float sh_loss[8];

    // pass A: min over 128 band mins
    float4 bm = ((const float4*)(g_tmin + (size_t)row * 128))[lane];
    float m = fminf(fminf(bm.x, bm.y), fminf(bm.z, bm.w));
    #pragma unroll
    for (int o = 16; o > 0; o >>= 1)
        m = fminf(m, __shfl_xor_sync(0xffffffffu, m, o));
    const float thr = m + MARGIN;

    int bmask = (bm.x <= thr ? 1 : 0) | (bm.y <= thr ? 2 : 0)
              | (bm.z <= thr ? 4 : 0) | (bm.w <= thr ? 8 : 0);

    // f row distributed across the warp: fr[q] = f[row, (q*32+lane)*4 ..+3]
    const float4* f4 = (const float4*)(f + (size_t)row * D);
    float4 fr[4];
    #pragma unroll
    for (int q = 0; q < 4; q++) fr[q] = f4[q * 32 + lane];

    // pass B: enumerate candidates in hot bands, exact fp32 rescore
    unsigned long long bestk = ~0ULL;
    unsigned bal = __ballot_sync(0xffffffffu, bmask != 0);
    while (bal) {
        const int s = __ffs(bal) - 1; bal &= bal - 1;
        int mb = __shfl_sync(0xffffffffu, bmask, s);
        while (mb) {
            const int q = __ffs(mb) - 1; mb &= mb - 1;
            const int band = s * 4 + q;
            const float sc_h = __half2float(
                g_scores[(size_t)row * KSZ + band * 32 + lane]);
            unsigned cb = __ballot_sync(0xffffffffu, sc_h <= thr);
            while (cb) {
                const int cs = __ffs(cb) - 1; cb &= cb - 1;
                const int cand = band * 32 + cs;
                const float4* k4 = (const float4*)(Kc + (size_t)cand * D);
                float ds = 0.0f;
                #pragma unroll
                for (int qq = 0; qq < 4; qq++) {
                    float4 a = fr[qq];
                    float4 kk = k4[qq * 32 + lane];
                    ds += a.x * kk.x + a.y * kk.y + a.z * kk.z + a.w * kk.w;
                }
                #pragma unroll
                for (int o = 16; o > 0; o >>= 1)
                    ds += __shfl_xor_sync(0xffffffffu, ds, o);
                const float sc = g_y2[cand] - 2.0f * ds;
                const unsigned long long key =
                    ((unsigned long long)fkey(sc) << 32) | (unsigned)cand;
                bestk = (key < bestk) ? key : bestk;
            }
        }
    }
    const int best = (int)(bestk & 0xFFFFFFFFULL);

    // fused gather: out = K[best], loss term, dw/count scatter
    const float4* kb4 = (const float4*)(Kc + (size_t)best * D);
    float4* ob = (float4*)(out + OFF_F) + (size_t)row * 128;
    float s = 0.0f;
    #pragma unroll
    for (int q = 0; q < 4; q++) {
        float4 kv = __ldg(kb4 + q * 32 + lane);
        ob[q * 32 + lane] = kv;
        float4 a = fr[q];
        float dx = kv.x - a.x, dy = kv.y - a.y, dz = kv.z - a.z, dwv = kv.w - a.w;
        s += dx * dx + dy * dy + dz * dz + dwv * dwv;
        float* dwp = g_dw + (size_t)best * D + (q * 32 + lane) * 4;
        atomicAdd(dwp + 0, a.x);
        atomicAdd(dwp + 1, a.y);
        atomicAdd(dwp + 2, a.z);
        atomicAdd(dwp + 3, a.w);
    }
    #pragma unroll
    for (int o = 16; o > 0; o >>= 1) s += __shfl_down_sync(0xffffffffu, s, o);
    if (lane == 0) {
        sh_loss[w] = s;
        atomicAdd(&g_counts[best], 1.0f);
    }
    __syncthreads();
    if (threadIdx.x == 0) {
        float tot = 0.0f;
        #pragma unroll
        for (int i = 0; i < 8; i++) tot += sh_loss[i];
        atomicAdd(&g_loss, (double)tot);
    }
}

// ---------------- kernel 5: new_ecs + n ----------------
__global__ void ecs_kernel(const float* __restrict__ ecs, float* __restrict__ out) {
    const int i = blockIdx.x * 256 + threadIdx.x;
    float newc = ecs[i] * 0.99f + 0.01f * g_counts[i];
    out[OFF_ECS + i] = newc;
    float s = newc;
    #pragma unroll
    for (int o = 16; o > 0; o >>= 1) s += __shfl_down_sync(0xffffffffu, s, o);
    __shared__ float sh[8];
    if ((threadIdx.x & 31) == 0) sh[threadIdx.x >> 5] = s;
    __syncthreads();
    if (threadIdx.x == 0) {
        float tot = 0.0f;
        #pragma unroll
        for (int w = 0; w < 8; w++) tot += sh[w];
        atomicAdd(&g_n, (double)tot);
    }
}

// ---------------- kernel 6: new_ema_w, new_K, loss ----------------
__global__ void final_kernel(const float* __restrict__ emaw, float* __restrict__ out) {
    const size_t i = (size_t)blockIdx.x * 256 + threadIdx.x;
    const int k = (int)(i >> 9);   // D = 512
    float neww = emaw[i] * 0.99f + 0.01f * g_dw[i];
    out[OFF_EMAW + i] = neww;
    float nn = (float)g_n;
    float newc = out[OFF_ECS + k];
    float smoothed = (newc + 1e-5f) / (nn + 4096.0f * 1e-5f) * nn;
    out[OFF_K + i] = neww / smoothed;
    if (i == 0)
        out[OFF_LOSS] = (float)(g_loss / ((double)N_ROWS * (double)D));
}

extern "C" void kernel_launch(void* const* d_in, const int* in_sizes, int n_in,
                              void* d_out, int out_size) {
    const float* f    = (const float*)d_in[0];  // [8,4096,512]
    const float* Kc   = (const float*)d_in[1];  // [4096,512]
    const float* ecs  = (const float*)d_in[2];  // [4096]
    const float* emaw = (const float*)d_in[3];  // [4096,512]
    float* out = (float*)d_out;

    cudaFuncSetAttribute(gemm_kernel, cudaFuncAttributeMaxDynamicSharedMemorySize, SMEM_DYN);

    split_kernel<<<(N_ROWS * D) / 256, 256>>>(f, Kc);
    y2_kernel<<<KSZ, 128>>>(Kc);
    gemm_kernel<<<(N_ROWS / 256) * CODT, 512, SMEM_DYN>>>();
    argmin_kernel<<<N_ROWS / 8, 256>>>(f, Kc, out);
    ecs_kernel<<<KSZ / 256, 256>>>(ecs, out);
    final_kernel<<<(KSZ * D) / 256, 256>>>(emaw, out);
}